// round 15
// baseline (speedup 1.0000x reference)
#include <cuda_runtime.h>
#include <cstdint>

#define NODE_EMB 128
#define EDGE_EMB 16
#define D_IN     160
#define N_MAX    100000
#define TILE_N   128
#define THREADS  512
#define AS_STRIDE 132
#define GRID_P   148

// finish kernel geometry
#define FIN_T    768
#define FIN_TILE 96
#define FIN_STRIDE 100     // 96 + 4 pad (16B-aligned rows)

// ---------------- device scratch ----------------
__device__ float g_rec [N_MAX * EDGE_EMB];
__device__ float g_sent[N_MAX * EDGE_EMB];
__device__ float g_rcnt[N_MAX];
__device__ float g_scnt[N_MAX];
__device__ float g_hp  [N_MAX * NODE_EMB];   // partial h = x@W1a + b1

// ---------------- packed f32x2 helpers ----------------
__device__ __forceinline__ unsigned long long pack2(float lo, float hi) {
    unsigned long long r;
    asm("mov.b64 %0, {%1, %2};" : "=l"(r) : "f"(lo), "f"(hi));
    return r;
}
__device__ __forceinline__ unsigned long long bcast2(float v) {
    unsigned long long r;
    asm("mov.b64 %0, {%1, %1};" : "=l"(r) : "f"(v));
    return r;
}
__device__ __forceinline__ void fma2(unsigned long long& d,
                                     unsigned long long a,
                                     unsigned long long b) {
    asm("fma.rn.f32x2 %0, %1, %2, %0;" : "+l"(d) : "l"(a), "l"(b));
}
__device__ __forceinline__ void unpack2(unsigned long long v, float& lo, float& hi) {
    asm("mov.b64 {%0, %1}, %2;" : "=f"(lo), "=f"(hi) : "l"(v));
}

// ---------------- kernel 1: zero accumulators ----------------
__global__ void zero_kernel(int N) {
    int stride = gridDim.x * blockDim.x;
    int t = blockIdx.x * blockDim.x + threadIdx.x;
    int total4 = N * EDGE_EMB / 4;
    float4 z = make_float4(0.f, 0.f, 0.f, 0.f);
    for (int i = t; i < total4; i += stride) {
        reinterpret_cast<float4*>(g_rec)[i]  = z;
        reinterpret_cast<float4*>(g_sent)[i] = z;
    }
    for (int i = t; i < N; i += stride) {
        g_rcnt[i] = 0.f;
        g_scnt[i] = 0.f;
    }
}

// ---------------- kernel 2: dual scatter (R4 proven full-grid form) ----------------
__global__ void scatter_kernel(const float4* __restrict__ edge_attr4,
                               const int* __restrict__ edge_index,
                               int E) {
    int t = blockIdx.x * blockDim.x + threadIdx.x;
    int total = E * 4;
    if (t >= total) return;
    int e = t >> 2;
    int q = t & 3;
    float4 v = edge_attr4[t];
    int row = edge_index[e];
    int col = edge_index[E + e];
    float* pr = &g_rec [row * EDGE_EMB + q * 4];
    float* ps = &g_sent[col * EDGE_EMB + q * 4];
    asm volatile("red.global.add.v4.f32 [%0], {%1, %2, %3, %4};"
                 :: "l"(pr), "f"(v.x), "f"(v.y), "f"(v.z), "f"(v.w) : "memory");
    asm volatile("red.global.add.v4.f32 [%0], {%1, %2, %3, %4};"
                 :: "l"(ps), "f"(v.x), "f"(v.y), "f"(v.z), "f"(v.w) : "memory");
    if (q == 0) {
        atomicAdd(&g_rcnt[row], 1.0f);
        atomicAdd(&g_scnt[col], 1.0f);
    }
}

// ---------------- kernel 3: persistent partial MLP (x-part only; edge-independent) ------
__global__ __launch_bounds__(THREADS, 1)
void hp_kernel(const float* __restrict__ x,
               const float* __restrict__ W1,
               const float* __restrict__ b1,
               int N, int np) {
    extern __shared__ float smem_f[];
    float* As  = smem_f;                          // x^T [128][AS_STRIDE]
    float* W1s = As + NODE_EMB * AS_STRIDE;       // W1 rows 0..127

    int tid = threadIdx.x;
    int tx = tid & 31;
    int ty = tid >> 5;

    for (int i = tid; i < (NODE_EMB * NODE_EMB) / 4; i += THREADS)
        reinterpret_cast<float4*>(W1s)[i] = reinterpret_cast<const float4*>(W1)[i];

    unsigned long long bias[4];
    #pragma unroll
    for (int cc = 0; cc < 4; ++cc) bias[cc] = bcast2(b1[tx + 32 * cc]);

    for (int tile = blockIdx.x; tile < np; tile += GRID_P) {
        int node0 = tile * TILE_N;
        __syncthreads();
        for (int idx = tid; idx < TILE_N * NODE_EMB; idx += THREADS) {
            int nl = idx >> 7;
            int k  = idx & 127;
            int n  = node0 + nl;
            As[k * AS_STRIDE + nl] = (n < N) ? x[(size_t)n * NODE_EMB + k] : 0.f;
        }
        __syncthreads();

        unsigned long long acc[4][4];
        #pragma unroll
        for (int cc = 0; cc < 4; ++cc) {
            #pragma unroll
            for (int j = 0; j < 4; ++j) acc[j][cc] = bias[cc];
        }
        #pragma unroll 4
        for (int k = 0; k < NODE_EMB; ++k) {
            const float* ar = &As[k * AS_STRIDE + ty * 8];
            ulonglong2 a01 = *reinterpret_cast<const ulonglong2*>(ar);
            ulonglong2 a23 = *reinterpret_cast<const ulonglong2*>(ar + 4);
            const float* wr = &W1s[k * NODE_EMB + tx];
            #pragma unroll
            for (int cc = 0; cc < 4; ++cc) {
                unsigned long long wd = bcast2(wr[32 * cc]);
                fma2(acc[0][cc], a01.x, wd);
                fma2(acc[1][cc], a01.y, wd);
                fma2(acc[2][cc], a23.x, wd);
                fma2(acc[3][cc], a23.y, wd);
            }
        }

        #pragma unroll
        for (int j = 0; j < 4; ++j) {
            int n0i = node0 + ty * 8 + 2 * j;
            #pragma unroll
            for (int cc = 0; cc < 4; ++cc) {
                float v0, v1;
                unpack2(acc[j][cc], v0, v1);
                int c = tx + 32 * cc;
                if (n0i < N)     g_hp[(size_t)n0i * NODE_EMB + c]       = v0;
                if (n0i + 1 < N) g_hp[(size_t)(n0i + 1) * NODE_EMB + c] = v1;
            }
        }
    }
}

// ---------------- kernel 4: persistent finish, 768 threads, 96-node tiles --------------
// 24 warps = 12 node-groups (8 nodes) x 2 col-halves; per-thread acc 4 node-pairs x 2 cols.
// Explicit k+1 prefetch (85-reg budget at 768 thr) pulls the 29-cyc LDS latency off the
// dependency chain — the R13 1024-thr config had no register room for this.
__global__ __launch_bounds__(FIN_T, 1)
void finish_kernel(const float* __restrict__ W1,
                   const float* __restrict__ W2,
                   const float* __restrict__ b2,
                   float* __restrict__ out,
                   int N, int np) {
    extern __shared__ float smem_f[];
    float* Hs   = smem_f;                              // h^T [128][FIN_STRIDE]
    float* Ms   = Hs + NODE_EMB * FIN_STRIDE;          // means^T [32][FIN_STRIDE]
    float* W1bs = Ms + 2 * EDGE_EMB * FIN_STRIDE;      // W1 rows 128..159 [32][128]
    float* W2s  = W1bs + 2 * EDGE_EMB * NODE_EMB;      // [128][128]

    int tid = threadIdx.x;
    int tx = tid & 31;
    int wid = tid >> 5;          // 0..23
    int wy = wid >> 1;           // node group: nodes [wy*8, wy*8+8)
    int wc = wid & 1;            // col half
    int c0 = tx + 64 * wc;       // cols c0 and c0+32

    for (int i = tid; i < (2 * EDGE_EMB * NODE_EMB) / 4; i += FIN_T)
        reinterpret_cast<float4*>(W1bs)[i] =
            reinterpret_cast<const float4*>(W1 + NODE_EMB * NODE_EMB)[i];
    for (int i = tid; i < (NODE_EMB * NODE_EMB) / 4; i += FIN_T)
        reinterpret_cast<float4*>(W2s)[i] = reinterpret_cast<const float4*>(W2)[i];

    unsigned long long bias2[2];
    bias2[0] = bcast2(b2[c0]);
    bias2[1] = bcast2(b2[c0 + 32]);

    for (int tile = blockIdx.x; tile < np; tile += GRID_P) {
        int node0 = tile * FIN_TILE;
        __syncthreads();

        // Stage means^T [k][node], k in 0..31
        for (int idx = tid; idx < FIN_TILE * 2 * EDGE_EMB; idx += FIN_T) {
            int nl = idx >> 5;
            int k  = idx & 31;
            int n  = node0 + nl;
            float v = 0.f;
            if (n < N) {
                if (k < EDGE_EMB) v = g_rec [(size_t)n * EDGE_EMB + k]              / fmaxf(g_rcnt[n], 1.f);
                else              v = g_sent[(size_t)n * EDGE_EMB + (k - EDGE_EMB)] / fmaxf(g_scnt[n], 1.f);
            }
            Ms[k * FIN_STRIDE + nl] = v;
        }
        __syncthreads();

        // Init acc from hp (coalesced LDG)
        unsigned long long acc[4][2];
        #pragma unroll
        for (int j = 0; j < 4; ++j) {
            int n0i = node0 + wy * 8 + 2 * j;
            #pragma unroll
            for (int cc = 0; cc < 2; ++cc) {
                int c = c0 + 32 * cc;
                float lo = (n0i < N)     ? g_hp[(size_t)n0i * NODE_EMB + c]       : 0.f;
                float hi = (n0i + 1 < N) ? g_hp[(size_t)(n0i + 1) * NODE_EMB + c] : 0.f;
                acc[j][cc] = pack2(lo, hi);
            }
        }

        // Phase 1: mean-driven 32 k-iterations, explicit prefetch
        {
            const float* mb = Ms + wy * 8;
            ulonglong2 a01 = *reinterpret_cast<const ulonglong2*>(mb);
            ulonglong2 a23 = *reinterpret_cast<const ulonglong2*>(mb + 4);
            unsigned long long w0 = bcast2(W1bs[c0]);
            unsigned long long w1 = bcast2(W1bs[c0 + 32]);
            #pragma unroll 4
            for (int k = 0; k < 2 * EDGE_EMB; ++k) {
                ulonglong2 b01 = a01, b23 = a23;
                unsigned long long v0 = w0, v1 = w1;
                if (k + 1 < 2 * EDGE_EMB) {
                    const float* mn = mb + (k + 1) * FIN_STRIDE;
                    a01 = *reinterpret_cast<const ulonglong2*>(mn);
                    a23 = *reinterpret_cast<const ulonglong2*>(mn + 4);
                    w0 = bcast2(W1bs[(k + 1) * NODE_EMB + c0]);
                    w1 = bcast2(W1bs[(k + 1) * NODE_EMB + c0 + 32]);
                }
                fma2(acc[0][0], b01.x, v0); fma2(acc[1][0], b01.y, v0);
                fma2(acc[2][0], b23.x, v0); fma2(acc[3][0], b23.y, v0);
                fma2(acc[0][1], b01.x, v1); fma2(acc[1][1], b01.y, v1);
                fma2(acc[2][1], b23.x, v1); fma2(acc[3][1], b23.y, v1);
            }
        }

        // LeakyReLU + store h^T[c][node]
        #pragma unroll
        for (int cc = 0; cc < 2; ++cc) {
            int c = c0 + 32 * cc;
            #pragma unroll
            for (int j = 0; j < 4; ++j) {
                float v0, v1;
                unpack2(acc[j][cc], v0, v1);
                v0 = (v0 >= 0.f) ? v0 : 0.01f * v0;
                v1 = (v1 >= 0.f) ? v1 : 0.01f * v1;
                *reinterpret_cast<unsigned long long*>(&Hs[c * FIN_STRIDE + wy * 8 + 2 * j])
                    = pack2(v0, v1);
            }
        }
        __syncthreads();

        // Phase 2: out = h @ W2 + b2, explicit prefetch
        #pragma unroll
        for (int cc = 0; cc < 2; ++cc) {
            #pragma unroll
            for (int j = 0; j < 4; ++j) acc[j][cc] = bias2[cc];
        }
        {
            const float* hb = Hs + wy * 8;
            ulonglong2 a01 = *reinterpret_cast<const ulonglong2*>(hb);
            ulonglong2 a23 = *reinterpret_cast<const ulonglong2*>(hb + 4);
            unsigned long long w0 = bcast2(W2s[c0]);
            unsigned long long w1 = bcast2(W2s[c0 + 32]);
            #pragma unroll 4
            for (int k = 0; k < NODE_EMB; ++k) {
                ulonglong2 b01 = a01, b23 = a23;
                unsigned long long v0 = w0, v1 = w1;
                if (k + 1 < NODE_EMB) {
                    const float* hn = hb + (k + 1) * FIN_STRIDE;
                    a01 = *reinterpret_cast<const ulonglong2*>(hn);
                    a23 = *reinterpret_cast<const ulonglong2*>(hn + 4);
                    w0 = bcast2(W2s[(k + 1) * NODE_EMB + c0]);
                    w1 = bcast2(W2s[(k + 1) * NODE_EMB + c0 + 32]);
                }
                fma2(acc[0][0], b01.x, v0); fma2(acc[1][0], b01.y, v0);
                fma2(acc[2][0], b23.x, v0); fma2(acc[3][0], b23.y, v0);
                fma2(acc[0][1], b01.x, v1); fma2(acc[1][1], b01.y, v1);
                fma2(acc[2][1], b23.x, v1); fma2(acc[3][1], b23.y, v1);
            }
        }

        #pragma unroll
        for (int j = 0; j < 4; ++j) {
            int n0i = node0 + wy * 8 + 2 * j;
            #pragma unroll
            for (int cc = 0; cc < 2; ++cc) {
                float v0, v1;
                unpack2(acc[j][cc], v0, v1);
                int c = c0 + 32 * cc;
                if (n0i < N)     out[(size_t)n0i * NODE_EMB + c]       = v0;
                if (n0i + 1 < N) out[(size_t)(n0i + 1) * NODE_EMB + c] = v1;
            }
        }
    }
}

// ---------------- launch: graph-level fork-join ----------------
extern "C" void kernel_launch(void* const* d_in, const int* in_sizes, int n_in,
                              void* d_out, int out_size) {
    const float* x          = (const float*)d_in[0];
    const int*   edge_index = (const int*)  d_in[1];
    const float* edge_attr  = (const float*)d_in[2];
    const float* W1         = (const float*)d_in[3];
    const float* b1         = (const float*)d_in[4];
    const float* W2         = (const float*)d_in[5];
    const float* b2         = (const float*)d_in[6];
    float* out = (float*)d_out;

    int N = in_sizes[0] / NODE_EMB;
    int E = in_sizes[2] / EDGE_EMB;
    int np_hp  = (N + TILE_N - 1) / TILE_N;
    int np_fin = (N + FIN_TILE - 1) / FIN_TILE;

    static cudaStream_t sB = nullptr;
    static cudaEvent_t e0 = nullptr, e1 = nullptr;
    static bool attrs_set = false;
    if (sB == nullptr) {
        cudaStreamCreateWithFlags(&sB, cudaStreamNonBlocking);
        cudaEventCreateWithFlags(&e0, cudaEventDisableTiming);
        cudaEventCreateWithFlags(&e1, cudaEventDisableTiming);
    }
    const int hp_smem  = (NODE_EMB * AS_STRIDE + NODE_EMB * NODE_EMB) * 4;          // 133120
    const int fin_smem = (NODE_EMB * FIN_STRIDE + 2 * EDGE_EMB * FIN_STRIDE
                          + 2 * EDGE_EMB * NODE_EMB + NODE_EMB * NODE_EMB) * 4;     // 145920
    if (!attrs_set) {
        cudaFuncSetAttribute(hp_kernel,     cudaFuncAttributeMaxDynamicSharedMemorySize, hp_smem);
        cudaFuncSetAttribute(finish_kernel, cudaFuncAttributeMaxDynamicSharedMemorySize, fin_smem);
        attrs_set = true;
    }

    // Fork
    cudaEventRecord(e0, 0);
    cudaStreamWaitEvent(sB, e0, 0);

    // Branch B: edge-independent partial MLP
    hp_kernel<<<GRID_P, THREADS, hp_smem, sB>>>(x, W1, b1, N, np_hp);
    cudaEventRecord(e1, sB);

    // Main branch: zero + scatter
    zero_kernel<<<1184, 256>>>(N);
    int total = E * 4;
    scatter_kernel<<<(total + 255) / 256, 256>>>(
        reinterpret_cast<const float4*>(edge_attr), edge_index, E);

    // Join, then finish
    cudaStreamWaitEvent(0, e1, 0);
    finish_kernel<<<GRID_P, FIN_T, fin_smem>>>(W1, W2, b2, out, N, np_fin);
}

// round 16
// speedup vs baseline: 1.0803x; 1.0803x over previous
#include <cuda_runtime.h>
#include <cstdint>

#define NODE_EMB 128
#define EDGE_EMB 16
#define D_IN     160
#define N_MAX    100000
#define TILE_N   128
#define THREADS  512
#define FIN_T    1024
#define AS_STRIDE 132
#define GRID_P   148

// ---------------- device scratch ----------------
__device__ float g_rec [N_MAX * EDGE_EMB];
__device__ float g_sent[N_MAX * EDGE_EMB];
__device__ float g_rcnt[N_MAX];
__device__ float g_scnt[N_MAX];
__device__ float g_hp  [N_MAX * NODE_EMB];   // partial h = x@W1a + b1

// ---------------- packed f32x2 helpers ----------------
__device__ __forceinline__ unsigned long long pack2(float lo, float hi) {
    unsigned long long r;
    asm("mov.b64 %0, {%1, %2};" : "=l"(r) : "f"(lo), "f"(hi));
    return r;
}
__device__ __forceinline__ unsigned long long bcast2(float v) {
    unsigned long long r;
    asm("mov.b64 %0, {%1, %1};" : "=l"(r) : "f"(v));
    return r;
}
__device__ __forceinline__ void fma2(unsigned long long& d,
                                     unsigned long long a,
                                     unsigned long long b) {
    asm("fma.rn.f32x2 %0, %1, %2, %0;" : "+l"(d) : "l"(a), "l"(b));
}
__device__ __forceinline__ void unpack2(unsigned long long v, float& lo, float& hi) {
    asm("mov.b64 {%0, %1}, %2;" : "=f"(lo), "=f"(hi) : "l"(v));
}

// ---------------- kernel 1: zero accumulators ----------------
__global__ void zero_kernel(int N) {
    int stride = gridDim.x * blockDim.x;
    int t = blockIdx.x * blockDim.x + threadIdx.x;
    int total4 = N * EDGE_EMB / 4;
    float4 z = make_float4(0.f, 0.f, 0.f, 0.f);
    for (int i = t; i < total4; i += stride) {
        reinterpret_cast<float4*>(g_rec)[i]  = z;
        reinterpret_cast<float4*>(g_sent)[i] = z;
    }
    for (int i = t; i < N; i += stride) {
        g_rcnt[i] = 0.f;
        g_scnt[i] = 0.f;
    }
}

// ---------------- kernel 2: dual scatter (R4 proven full-grid form) ----------------
__global__ void scatter_kernel(const float4* __restrict__ edge_attr4,
                               const int* __restrict__ edge_index,
                               int E) {
    int t = blockIdx.x * blockDim.x + threadIdx.x;
    int total = E * 4;
    if (t >= total) return;
    int e = t >> 2;
    int q = t & 3;
    float4 v = edge_attr4[t];
    int row = edge_index[e];
    int col = edge_index[E + e];
    float* pr = &g_rec [row * EDGE_EMB + q * 4];
    float* ps = &g_sent[col * EDGE_EMB + q * 4];
    asm volatile("red.global.add.v4.f32 [%0], {%1, %2, %3, %4};"
                 :: "l"(pr), "f"(v.x), "f"(v.y), "f"(v.z), "f"(v.w) : "memory");
    asm volatile("red.global.add.v4.f32 [%0], {%1, %2, %3, %4};"
                 :: "l"(ps), "f"(v.x), "f"(v.y), "f"(v.z), "f"(v.w) : "memory");
    if (q == 0) {
        atomicAdd(&g_rcnt[row], 1.0f);
        atomicAdd(&g_scnt[col], 1.0f);
    }
}

// ---------------- kernel 3: persistent partial MLP (x-part only; edge-independent) ------
__global__ __launch_bounds__(THREADS, 1)
void hp_kernel(const float* __restrict__ x,
               const float* __restrict__ W1,
               const float* __restrict__ b1,
               int N, int np) {
    extern __shared__ float smem_f[];
    float* As  = smem_f;                          // x^T [128][AS_STRIDE]
    float* W1s = As + NODE_EMB * AS_STRIDE;       // W1 rows 0..127

    int tid = threadIdx.x;
    int tx = tid & 31;
    int ty = tid >> 5;

    for (int i = tid; i < (NODE_EMB * NODE_EMB) / 4; i += THREADS)
        reinterpret_cast<float4*>(W1s)[i] = reinterpret_cast<const float4*>(W1)[i];

    unsigned long long bias[4];
    #pragma unroll
    for (int cc = 0; cc < 4; ++cc) bias[cc] = bcast2(b1[tx + 32 * cc]);

    for (int tile = blockIdx.x; tile < np; tile += GRID_P) {
        int node0 = tile * TILE_N;
        __syncthreads();
        for (int idx = tid; idx < TILE_N * NODE_EMB; idx += THREADS) {
            int nl = idx >> 7;
            int k  = idx & 127;
            int n  = node0 + nl;
            As[k * AS_STRIDE + nl] = (n < N) ? x[(size_t)n * NODE_EMB + k] : 0.f;
        }
        __syncthreads();

        unsigned long long acc[4][4];
        #pragma unroll
        for (int cc = 0; cc < 4; ++cc) {
            #pragma unroll
            for (int j = 0; j < 4; ++j) acc[j][cc] = bias[cc];
        }
        #pragma unroll 4
        for (int k = 0; k < NODE_EMB; ++k) {
            const float* ar = &As[k * AS_STRIDE + ty * 8];
            ulonglong2 a01 = *reinterpret_cast<const ulonglong2*>(ar);
            ulonglong2 a23 = *reinterpret_cast<const ulonglong2*>(ar + 4);
            const float* wr = &W1s[k * NODE_EMB + tx];
            #pragma unroll
            for (int cc = 0; cc < 4; ++cc) {
                unsigned long long wd = bcast2(wr[32 * cc]);
                fma2(acc[0][cc], a01.x, wd);
                fma2(acc[1][cc], a01.y, wd);
                fma2(acc[2][cc], a23.x, wd);
                fma2(acc[3][cc], a23.y, wd);
            }
        }

        #pragma unroll
        for (int j = 0; j < 4; ++j) {
            int n0i = node0 + ty * 8 + 2 * j;
            #pragma unroll
            for (int cc = 0; cc < 4; ++cc) {
                float v0, v1;
                unpack2(acc[j][cc], v0, v1);
                int c = tx + 32 * cc;
                if (n0i < N)     g_hp[(size_t)n0i * NODE_EMB + c]       = v0;
                if (n0i + 1 < N) g_hp[(size_t)(n0i + 1) * NODE_EMB + c] = v1;
            }
        }
    }
}

// ---------------- kernel 4: persistent finish, 1024 threads (R13 form, frozen) ----------
// Warp wid: node group wy = wid>>1 (8 nodes), col half wc = wid&1.
// Only change vs R13: g_hp loads hoisted ABOVE the Ms staging loop so their
// global-memory latency overlaps staging + barrier instead of phase 1.
__global__ __launch_bounds__(FIN_T, 1)
void finish_kernel(const float* __restrict__ W1,
                   const float* __restrict__ W2,
                   const float* __restrict__ b2,
                   float* __restrict__ out,
                   int N, int np) {
    extern __shared__ float smem_f[];
    float* Hs   = smem_f;                              // h^T [128][AS_STRIDE]
    float* Ms   = Hs + NODE_EMB * AS_STRIDE;           // means^T [32][AS_STRIDE]
    float* W1bs = Ms + 2 * EDGE_EMB * AS_STRIDE;       // W1 rows 128..159
    float* W2s  = W1bs + 2 * EDGE_EMB * NODE_EMB;      // [128][128]

    int tid = threadIdx.x;
    int tx = tid & 31;
    int wid = tid >> 5;
    int wy = wid >> 1;          // node group: nodes [wy*8, wy*8+8)
    int wc = wid & 1;           // col half
    int c0 = tx + 64 * wc;      // cols c0 and c0+32

    for (int i = tid; i < (2 * EDGE_EMB * NODE_EMB) / 4; i += FIN_T)
        reinterpret_cast<float4*>(W1bs)[i] =
            reinterpret_cast<const float4*>(W1 + NODE_EMB * NODE_EMB)[i];
    for (int i = tid; i < (NODE_EMB * NODE_EMB) / 4; i += FIN_T)
        reinterpret_cast<float4*>(W2s)[i] = reinterpret_cast<const float4*>(W2)[i];

    unsigned long long bias2[2];
    bias2[0] = bcast2(b2[c0]);
    bias2[1] = bcast2(b2[c0 + 32]);

    for (int tile = blockIdx.x; tile < np; tile += GRID_P) {
        int node0 = tile * TILE_N;
        __syncthreads();

        // Hoisted: init acc from hp (independent of Ms) — latency overlaps staging below.
        unsigned long long acc[4][2];
        #pragma unroll
        for (int j = 0; j < 4; ++j) {
            int n0i = node0 + wy * 8 + 2 * j;
            #pragma unroll
            for (int cc = 0; cc < 2; ++cc) {
                int c = c0 + 32 * cc;
                float lo = (n0i < N)     ? g_hp[(size_t)n0i * NODE_EMB + c]       : 0.f;
                float hi = (n0i + 1 < N) ? g_hp[(size_t)(n0i + 1) * NODE_EMB + c] : 0.f;
                acc[j][cc] = pack2(lo, hi);
            }
        }

        // Stage means^T [k][node], k in 0..31
        for (int idx = tid; idx < TILE_N * 2 * EDGE_EMB; idx += FIN_T) {
            int nl = idx >> 5;
            int k  = idx & 31;
            int n  = node0 + nl;
            float v = 0.f;
            if (n < N) {
                if (k < EDGE_EMB) v = g_rec [(size_t)n * EDGE_EMB + k]              / fmaxf(g_rcnt[n], 1.f);
                else              v = g_sent[(size_t)n * EDGE_EMB + (k - EDGE_EMB)] / fmaxf(g_scnt[n], 1.f);
            }
            Ms[k * AS_STRIDE + nl] = v;
        }
        __syncthreads();

        // Mean-driven k-iterations (32)
        #pragma unroll 4
        for (int k = 0; k < 2 * EDGE_EMB; ++k) {
            const float* ar = &Ms[k * AS_STRIDE + wy * 8];
            ulonglong2 a01 = *reinterpret_cast<const ulonglong2*>(ar);
            ulonglong2 a23 = *reinterpret_cast<const ulonglong2*>(ar + 4);
            const float* wr = &W1bs[k * NODE_EMB + c0];
            #pragma unroll
            for (int cc = 0; cc < 2; ++cc) {
                unsigned long long wd = bcast2(wr[32 * cc]);
                fma2(acc[0][cc], a01.x, wd);
                fma2(acc[1][cc], a01.y, wd);
                fma2(acc[2][cc], a23.x, wd);
                fma2(acc[3][cc], a23.y, wd);
            }
        }

        // LeakyReLU + store h^T[c][node]
        #pragma unroll
        for (int cc = 0; cc < 2; ++cc) {
            int c = c0 + 32 * cc;
            #pragma unroll
            for (int j = 0; j < 4; ++j) {
                float v0, v1;
                unpack2(acc[j][cc], v0, v1);
                v0 = (v0 >= 0.f) ? v0 : 0.01f * v0;
                v1 = (v1 >= 0.f) ? v1 : 0.01f * v1;
                *reinterpret_cast<unsigned long long*>(&Hs[c * AS_STRIDE + wy * 8 + 2 * j])
                    = pack2(v0, v1);
            }
        }
        __syncthreads();

        // Phase 2: out = h @ W2 + b2
        #pragma unroll
        for (int cc = 0; cc < 2; ++cc) {
            #pragma unroll
            for (int j = 0; j < 4; ++j) acc[j][cc] = bias2[cc];
        }
        #pragma unroll 4
        for (int k = 0; k < NODE_EMB; ++k) {
            const float* ar = &Hs[k * AS_STRIDE + wy * 8];
            ulonglong2 a01 = *reinterpret_cast<const ulonglong2*>(ar);
            ulonglong2 a23 = *reinterpret_cast<const ulonglong2*>(ar + 4);
            const float* wr = &W2s[k * NODE_EMB + c0];
            #pragma unroll
            for (int cc = 0; cc < 2; ++cc) {
                unsigned long long wd = bcast2(wr[32 * cc]);
                fma2(acc[0][cc], a01.x, wd);
                fma2(acc[1][cc], a01.y, wd);
                fma2(acc[2][cc], a23.x, wd);
                fma2(acc[3][cc], a23.y, wd);
            }
        }

        #pragma unroll
        for (int j = 0; j < 4; ++j) {
            int n0i = node0 + wy * 8 + 2 * j;
            #pragma unroll
            for (int cc = 0; cc < 2; ++cc) {
                float v0, v1;
                unpack2(acc[j][cc], v0, v1);
                int c = c0 + 32 * cc;
                if (n0i < N)     out[(size_t)n0i * NODE_EMB + c]       = v0;
                if (n0i + 1 < N) out[(size_t)(n0i + 1) * NODE_EMB + c] = v1;
            }
        }
    }
}

// ---------------- launch: graph-level fork-join ----------------
extern "C" void kernel_launch(void* const* d_in, const int* in_sizes, int n_in,
                              void* d_out, int out_size) {
    const float* x          = (const float*)d_in[0];
    const int*   edge_index = (const int*)  d_in[1];
    const float* edge_attr  = (const float*)d_in[2];
    const float* W1         = (const float*)d_in[3];
    const float* b1         = (const float*)d_in[4];
    const float* W2         = (const float*)d_in[5];
    const float* b2         = (const float*)d_in[6];
    float* out = (float*)d_out;

    int N = in_sizes[0] / NODE_EMB;
    int E = in_sizes[2] / EDGE_EMB;
    int np = (N + TILE_N - 1) / TILE_N;

    static cudaStream_t sB = nullptr;
    static cudaEvent_t e0 = nullptr, e1 = nullptr;
    static bool attrs_set = false;
    if (sB == nullptr) {
        cudaStreamCreateWithFlags(&sB, cudaStreamNonBlocking);
        cudaEventCreateWithFlags(&e0, cudaEventDisableTiming);
        cudaEventCreateWithFlags(&e1, cudaEventDisableTiming);
    }
    const int hp_smem  = (NODE_EMB * AS_STRIDE + NODE_EMB * NODE_EMB) * 4;        // 133120
    const int fin_smem = (NODE_EMB * AS_STRIDE + 2 * EDGE_EMB * AS_STRIDE
                          + 2 * EDGE_EMB * NODE_EMB + NODE_EMB * NODE_EMB) * 4;   // 166400
    if (!attrs_set) {
        cudaFuncSetAttribute(hp_kernel,     cudaFuncAttributeMaxDynamicSharedMemorySize, hp_smem);
        cudaFuncSetAttribute(finish_kernel, cudaFuncAttributeMaxDynamicSharedMemorySize, fin_smem);
        attrs_set = true;
    }

    // Fork
    cudaEventRecord(e0, 0);
    cudaStreamWaitEvent(sB, e0, 0);

    // Branch B: edge-independent partial MLP
    hp_kernel<<<GRID_P, THREADS, hp_smem, sB>>>(x, W1, b1, N, np);
    cudaEventRecord(e1, sB);

    // Main branch: zero + scatter
    zero_kernel<<<1184, 256>>>(N);
    int total = E * 4;
    scatter_kernel<<<(total + 255) / 256, 256>>>(
        reinterpret_cast<const float4*>(edge_attr), edge_index, E);

    // Join, then finish
    cudaStreamWaitEvent(0, e1, 0);
    finish_kernel<<<GRID_P, FIN_T, fin_smem>>>(W1, W2, b2, out, N, np);
}

// round 17
// speedup vs baseline: 1.0877x; 1.0069x over previous
#include <cuda_runtime.h>
#include <cstdint>

#define NODE_EMB 128
#define EDGE_EMB 16
#define D_IN     160
#define N_MAX    100000
#define TILE_N   128
#define THREADS  512
#define FIN_T    1024
#define AS_STRIDE 132
#define GRID_P   148

// ---------------- device scratch ----------------
// Zero-initialized at module load; finish_kernel restores zeros after each use,
// so the zero-invariant holds across the correctness call and every graph replay.
__device__ float g_rec [N_MAX * EDGE_EMB];
__device__ float g_sent[N_MAX * EDGE_EMB];
__device__ float g_rcnt[N_MAX];
__device__ float g_scnt[N_MAX];
__device__ float g_hp  [N_MAX * NODE_EMB];   // partial h = x@W1a + b1

// ---------------- packed f32x2 helpers ----------------
__device__ __forceinline__ unsigned long long pack2(float lo, float hi) {
    unsigned long long r;
    asm("mov.b64 %0, {%1, %2};" : "=l"(r) : "f"(lo), "f"(hi));
    return r;
}
__device__ __forceinline__ unsigned long long bcast2(float v) {
    unsigned long long r;
    asm("mov.b64 %0, {%1, %1};" : "=l"(r) : "f"(v));
    return r;
}
__device__ __forceinline__ void fma2(unsigned long long& d,
                                     unsigned long long a,
                                     unsigned long long b) {
    asm("fma.rn.f32x2 %0, %1, %2, %0;" : "+l"(d) : "l"(a), "l"(b));
}
__device__ __forceinline__ void unpack2(unsigned long long v, float& lo, float& hi) {
    asm("mov.b64 {%0, %1}, %2;" : "=f"(lo), "=f"(hi) : "l"(v));
}

// ---------------- kernel 1: dual scatter (R4 proven full-grid form) ----------------
__global__ void scatter_kernel(const float4* __restrict__ edge_attr4,
                               const int* __restrict__ edge_index,
                               int E) {
    int t = blockIdx.x * blockDim.x + threadIdx.x;
    int total = E * 4;
    if (t >= total) return;
    int e = t >> 2;
    int q = t & 3;
    float4 v = edge_attr4[t];
    int row = edge_index[e];
    int col = edge_index[E + e];
    float* pr = &g_rec [row * EDGE_EMB + q * 4];
    float* ps = &g_sent[col * EDGE_EMB + q * 4];
    asm volatile("red.global.add.v4.f32 [%0], {%1, %2, %3, %4};"
                 :: "l"(pr), "f"(v.x), "f"(v.y), "f"(v.z), "f"(v.w) : "memory");
    asm volatile("red.global.add.v4.f32 [%0], {%1, %2, %3, %4};"
                 :: "l"(ps), "f"(v.x), "f"(v.y), "f"(v.z), "f"(v.w) : "memory");
    if (q == 0) {
        atomicAdd(&g_rcnt[row], 1.0f);
        atomicAdd(&g_scnt[col], 1.0f);
    }
}

// ---------------- kernel 2: persistent partial MLP (x-part only; edge-independent) ------
__global__ __launch_bounds__(THREADS, 1)
void hp_kernel(const float* __restrict__ x,
               const float* __restrict__ W1,
               const float* __restrict__ b1,
               int N, int np) {
    extern __shared__ float smem_f[];
    float* As  = smem_f;                          // x^T [128][AS_STRIDE]
    float* W1s = As + NODE_EMB * AS_STRIDE;       // W1 rows 0..127

    int tid = threadIdx.x;
    int tx = tid & 31;
    int ty = tid >> 5;

    for (int i = tid; i < (NODE_EMB * NODE_EMB) / 4; i += THREADS)
        reinterpret_cast<float4*>(W1s)[i] = reinterpret_cast<const float4*>(W1)[i];

    unsigned long long bias[4];
    #pragma unroll
    for (int cc = 0; cc < 4; ++cc) bias[cc] = bcast2(b1[tx + 32 * cc]);

    for (int tile = blockIdx.x; tile < np; tile += GRID_P) {
        int node0 = tile * TILE_N;
        __syncthreads();
        for (int idx = tid; idx < TILE_N * NODE_EMB; idx += THREADS) {
            int nl = idx >> 7;
            int k  = idx & 127;
            int n  = node0 + nl;
            As[k * AS_STRIDE + nl] = (n < N) ? x[(size_t)n * NODE_EMB + k] : 0.f;
        }
        __syncthreads();

        unsigned long long acc[4][4];
        #pragma unroll
        for (int cc = 0; cc < 4; ++cc) {
            #pragma unroll
            for (int j = 0; j < 4; ++j) acc[j][cc] = bias[cc];
        }
        #pragma unroll 4
        for (int k = 0; k < NODE_EMB; ++k) {
            const float* ar = &As[k * AS_STRIDE + ty * 8];
            ulonglong2 a01 = *reinterpret_cast<const ulonglong2*>(ar);
            ulonglong2 a23 = *reinterpret_cast<const ulonglong2*>(ar + 4);
            const float* wr = &W1s[k * NODE_EMB + tx];
            #pragma unroll
            for (int cc = 0; cc < 4; ++cc) {
                unsigned long long wd = bcast2(wr[32 * cc]);
                fma2(acc[0][cc], a01.x, wd);
                fma2(acc[1][cc], a01.y, wd);
                fma2(acc[2][cc], a23.x, wd);
                fma2(acc[3][cc], a23.y, wd);
            }
        }

        #pragma unroll
        for (int j = 0; j < 4; ++j) {
            int n0i = node0 + ty * 8 + 2 * j;
            #pragma unroll
            for (int cc = 0; cc < 4; ++cc) {
                float v0, v1;
                unpack2(acc[j][cc], v0, v1);
                int c = tx + 32 * cc;
                if (n0i < N)     g_hp[(size_t)n0i * NODE_EMB + c]       = v0;
                if (n0i + 1 < N) g_hp[(size_t)(n0i + 1) * NODE_EMB + c] = v1;
            }
        }
    }
}

// ---------------- kernel 3: persistent finish (R13 frozen form + self-zeroing) ----------
// Warp wid: node group wy = wid>>1 (8 nodes), col half wc = wid&1.
// Self-zeroing: each g_rec/g_sent element is zeroed by the thread that consumed it;
// counts zeroed once per node after the staging barrier (tiles partition nodes).
__global__ __launch_bounds__(FIN_T, 1)
void finish_kernel(const float* __restrict__ W1,
                   const float* __restrict__ W2,
                   const float* __restrict__ b2,
                   float* __restrict__ out,
                   int N, int np) {
    extern __shared__ float smem_f[];
    float* Hs   = smem_f;                              // h^T [128][AS_STRIDE]
    float* Ms   = Hs + NODE_EMB * AS_STRIDE;           // means^T [32][AS_STRIDE]
    float* W1bs = Ms + 2 * EDGE_EMB * AS_STRIDE;       // W1 rows 128..159
    float* W2s  = W1bs + 2 * EDGE_EMB * NODE_EMB;      // [128][128]

    int tid = threadIdx.x;
    int tx = tid & 31;
    int wid = tid >> 5;
    int wy = wid >> 1;          // node group: nodes [wy*8, wy*8+8)
    int wc = wid & 1;           // col half
    int c0 = tx + 64 * wc;      // cols c0 and c0+32

    for (int i = tid; i < (2 * EDGE_EMB * NODE_EMB) / 4; i += FIN_T)
        reinterpret_cast<float4*>(W1bs)[i] =
            reinterpret_cast<const float4*>(W1 + NODE_EMB * NODE_EMB)[i];
    for (int i = tid; i < (NODE_EMB * NODE_EMB) / 4; i += FIN_T)
        reinterpret_cast<float4*>(W2s)[i] = reinterpret_cast<const float4*>(W2)[i];

    unsigned long long bias2[2];
    bias2[0] = bcast2(b2[c0]);
    bias2[1] = bcast2(b2[c0 + 32]);

    for (int tile = blockIdx.x; tile < np; tile += GRID_P) {
        int node0 = tile * TILE_N;
        __syncthreads();

        // Init acc from hp (independent of Ms) — latency overlaps staging below.
        unsigned long long acc[4][2];
        #pragma unroll
        for (int j = 0; j < 4; ++j) {
            int n0i = node0 + wy * 8 + 2 * j;
            #pragma unroll
            for (int cc = 0; cc < 2; ++cc) {
                int c = c0 + 32 * cc;
                float lo = (n0i < N)     ? g_hp[(size_t)n0i * NODE_EMB + c]       : 0.f;
                float hi = (n0i + 1 < N) ? g_hp[(size_t)(n0i + 1) * NODE_EMB + c] : 0.f;
                acc[j][cc] = pack2(lo, hi);
            }
        }

        // Stage means^T [k][node]; zero each consumed accumulator element in place.
        for (int idx = tid; idx < TILE_N * 2 * EDGE_EMB; idx += FIN_T) {
            int nl = idx >> 5;
            int k  = idx & 31;
            int n  = node0 + nl;
            float v = 0.f;
            if (n < N) {
                if (k < EDGE_EMB) {
                    size_t gi = (size_t)n * EDGE_EMB + k;
                    v = g_rec[gi] / fmaxf(g_rcnt[n], 1.f);
                    g_rec[gi] = 0.f;
                } else {
                    size_t gi = (size_t)n * EDGE_EMB + (k - EDGE_EMB);
                    v = g_sent[gi] / fmaxf(g_scnt[n], 1.f);
                    g_sent[gi] = 0.f;
                }
            }
            Ms[k * AS_STRIDE + nl] = v;
        }
        __syncthreads();
        // Counts: zero once per node (all 32 readers are past the barrier).
        for (int nl = tid; nl < TILE_N; nl += FIN_T) {
            int n = node0 + nl;
            if (n < N) { g_rcnt[n] = 0.f; g_scnt[n] = 0.f; }
        }

        // Mean-driven k-iterations (32)
        #pragma unroll 4
        for (int k = 0; k < 2 * EDGE_EMB; ++k) {
            const float* ar = &Ms[k * AS_STRIDE + wy * 8];
            ulonglong2 a01 = *reinterpret_cast<const ulonglong2*>(ar);
            ulonglong2 a23 = *reinterpret_cast<const ulonglong2*>(ar + 4);
            const float* wr = &W1bs[k * NODE_EMB + c0];
            #pragma unroll
            for (int cc = 0; cc < 2; ++cc) {
                unsigned long long wd = bcast2(wr[32 * cc]);
                fma2(acc[0][cc], a01.x, wd);
                fma2(acc[1][cc], a01.y, wd);
                fma2(acc[2][cc], a23.x, wd);
                fma2(acc[3][cc], a23.y, wd);
            }
        }

        // LeakyReLU + store h^T[c][node]
        #pragma unroll
        for (int cc = 0; cc < 2; ++cc) {
            int c = c0 + 32 * cc;
            #pragma unroll
            for (int j = 0; j < 4; ++j) {
                float v0, v1;
                unpack2(acc[j][cc], v0, v1);
                v0 = (v0 >= 0.f) ? v0 : 0.01f * v0;
                v1 = (v1 >= 0.f) ? v1 : 0.01f * v1;
                *reinterpret_cast<unsigned long long*>(&Hs[c * AS_STRIDE + wy * 8 + 2 * j])
                    = pack2(v0, v1);
            }
        }
        __syncthreads();

        // Phase 2: out = h @ W2 + b2
        #pragma unroll
        for (int cc = 0; cc < 2; ++cc) {
            #pragma unroll
            for (int j = 0; j < 4; ++j) acc[j][cc] = bias2[cc];
        }
        #pragma unroll 4
        for (int k = 0; k < NODE_EMB; ++k) {
            const float* ar = &Hs[k * AS_STRIDE + wy * 8];
            ulonglong2 a01 = *reinterpret_cast<const ulonglong2*>(ar);
            ulonglong2 a23 = *reinterpret_cast<const ulonglong2*>(ar + 4);
            const float* wr = &W2s[k * NODE_EMB + c0];
            #pragma unroll
            for (int cc = 0; cc < 2; ++cc) {
                unsigned long long wd = bcast2(wr[32 * cc]);
                fma2(acc[0][cc], a01.x, wd);
                fma2(acc[1][cc], a01.y, wd);
                fma2(acc[2][cc], a23.x, wd);
                fma2(acc[3][cc], a23.y, wd);
            }
        }

        #pragma unroll
        for (int j = 0; j < 4; ++j) {
            int n0i = node0 + wy * 8 + 2 * j;
            #pragma unroll
            for (int cc = 0; cc < 2; ++cc) {
                float v0, v1;
                unpack2(acc[j][cc], v0, v1);
                int c = c0 + 32 * cc;
                if (n0i < N)     out[(size_t)n0i * NODE_EMB + c]       = v0;
                if (n0i + 1 < N) out[(size_t)(n0i + 1) * NODE_EMB + c] = v1;
            }
        }
    }
}

// ---------------- launch: graph-level fork-join (no zero kernel) ----------------
extern "C" void kernel_launch(void* const* d_in, const int* in_sizes, int n_in,
                              void* d_out, int out_size) {
    const float* x          = (const float*)d_in[0];
    const int*   edge_index = (const int*)  d_in[1];
    const float* edge_attr  = (const float*)d_in[2];
    const float* W1         = (const float*)d_in[3];
    const float* b1         = (const float*)d_in[4];
    const float* W2         = (const float*)d_in[5];
    const float* b2         = (const float*)d_in[6];
    float* out = (float*)d_out;

    int N = in_sizes[0] / NODE_EMB;
    int E = in_sizes[2] / EDGE_EMB;
    int np = (N + TILE_N - 1) / TILE_N;

    static cudaStream_t sB = nullptr;
    static cudaEvent_t e0 = nullptr, e1 = nullptr;
    static bool attrs_set = false;
    if (sB == nullptr) {
        cudaStreamCreateWithFlags(&sB, cudaStreamNonBlocking);
        cudaEventCreateWithFlags(&e0, cudaEventDisableTiming);
        cudaEventCreateWithFlags(&e1, cudaEventDisableTiming);
    }
    const int hp_smem  = (NODE_EMB * AS_STRIDE + NODE_EMB * NODE_EMB) * 4;        // 133120
    const int fin_smem = (NODE_EMB * AS_STRIDE + 2 * EDGE_EMB * AS_STRIDE
                          + 2 * EDGE_EMB * NODE_EMB + NODE_EMB * NODE_EMB) * 4;   // 166400
    if (!attrs_set) {
        cudaFuncSetAttribute(hp_kernel,     cudaFuncAttributeMaxDynamicSharedMemorySize, hp_smem);
        cudaFuncSetAttribute(finish_kernel, cudaFuncAttributeMaxDynamicSharedMemorySize, fin_smem);
        attrs_set = true;
    }

    // Fork
    cudaEventRecord(e0, 0);
    cudaStreamWaitEvent(sB, e0, 0);

    // Branch B: edge-independent partial MLP
    hp_kernel<<<GRID_P, THREADS, hp_smem, sB>>>(x, W1, b1, N, np);
    cudaEventRecord(e1, sB);

    // Main branch: scatter (accumulators are already zero — invariant maintained
    // by module-load zero-init + finish_kernel's self-zeroing)
    int total = E * 4;
    scatter_kernel<<<(total + 255) / 256, 256>>>(
        reinterpret_cast<const float4*>(edge_attr), edge_index, E);

    // Join, then finish
    cudaStreamWaitEvent(0, e1, 0);
    finish_kernel<<<GRID_P, FIN_T, fin_smem>>>(W1, W2, b2, out, N, np);
}